// round 6
// baseline (speedup 1.0000x reference)
#include <cuda_runtime.h>
#include <cstdint>

// Pendulum2 constrained-dynamics RHS, closed form.
// Two rows (64B) per thread via two front-batched Blackwell 256-bit loads:
// warp-wide covers 2KB fully dense, per-thread MLP=2, default caching
// (R5 showed .cs store hints regress; reverted).
//
//   det' = 2 s1 s2 - c^2 = s1 s2 + u^2   (u = x0 dy - x1 dx; cancellation-free)
//   R1 = -20 x1 + 2|v01|^2 ; R2 = 2|dv|^2 ; lam = 2.5 adj(L')R/det'

struct F8 { float x0,x1,x2,x3,v0,v1,v2,v3; };

__device__ __forceinline__ F8 ldv8(const float* p) {
    uint32_t r0,r1,r2,r3,r4,r5,r6,r7;
    asm("ld.global.v8.b32 {%0,%1,%2,%3,%4,%5,%6,%7}, [%8];"
        : "=r"(r0), "=r"(r1), "=r"(r2), "=r"(r3),
          "=r"(r4), "=r"(r5), "=r"(r6), "=r"(r7)
        : "l"(p));
    F8 f;
    f.x0 = __uint_as_float(r0); f.x1 = __uint_as_float(r1);
    f.x2 = __uint_as_float(r2); f.x3 = __uint_as_float(r3);
    f.v0 = __uint_as_float(r4); f.v1 = __uint_as_float(r5);
    f.v2 = __uint_as_float(r6); f.v3 = __uint_as_float(r7);
    return f;
}

__device__ __forceinline__ void stv8(float* q, float v0, float v1, float v2, float v3,
                                     float a0, float a1, float a2, float a3) {
    asm volatile("st.global.v8.b32 [%0], {%1,%2,%3,%4,%5,%6,%7,%8};"
                 :: "l"(q),
                    "r"(__float_as_uint(v0)), "r"(__float_as_uint(v1)),
                    "r"(__float_as_uint(v2)), "r"(__float_as_uint(v3)),
                    "r"(__float_as_uint(a0)), "r"(__float_as_uint(a1)),
                    "r"(__float_as_uint(a2)), "r"(__float_as_uint(a3))
                 : "memory");
}

__device__ __forceinline__ void solve(const F8& f, float& a0, float& a1,
                                      float& a2, float& a3) {
    float dx  = f.x0 - f.x2;
    float dy  = f.x1 - f.x3;
    float dv0 = f.v0 - f.v2;
    float dv1 = f.v1 - f.v3;

    float s1 = fmaf(f.x0, f.x0, f.x1 * f.x1);
    float s2 = fmaf(dx, dx, dy * dy);
    float c  = fmaf(f.x0, dx, f.x1 * dy);
    float u  = fmaf(f.x0, dy, -(f.x1 * dx));

    float R1 = fmaf(2.0f, fmaf(f.v0, f.v0, f.v1 * f.v1), -20.0f * f.x1);
    float R2 = 2.0f * fmaf(dv0, dv0, dv1 * dv1);

    float det = fmaf(s1, s2, u * u);   // = 2*s1*s2 - c^2, stable form
    float inv = 2.5f / det;

    float lam1 = fmaf(2.0f * s2, R1, -(c * R2)) * inv;
    float lam2 = fmaf(s1, R2, -(c * R1)) * inv;

    a0 = -0.2f * fmaf(f.x0, lam1, dx * lam2);
    a1 = fmaf(-0.2f, fmaf(f.x1, lam1, dy * lam2), -10.0f);
    a2 = 0.2f * (dx * lam2);
    a3 = fmaf(0.2f, dy * lam2, -10.0f);
}

__global__ void __launch_bounds__(256)
pendulum2_kernel(const float* __restrict__ in, float* __restrict__ out, int bs)
{
    int i = blockIdx.x * blockDim.x + threadIdx.x;   // rows 2i, 2i+1
    int r0 = 2 * i;
    if (r0 >= bs) return;

    const float* p = in + 16u * (uint32_t)i;
    F8 f0 = ldv8(p);
    bool two = (r0 + 1 < bs);
    F8 f1;
    if (two) f1 = ldv8(p + 8);

    float a0, a1, a2, a3;
    solve(f0, a0, a1, a2, a3);
    float* q = out + 16u * (uint32_t)i;
    stv8(q, f0.v0, f0.v1, f0.v2, f0.v3, a0, a1, a2, a3);

    if (two) {
        float b0, b1, b2, b3;
        solve(f1, b0, b1, b2, b3);
        stv8(q + 8, f1.v0, f1.v1, f1.v2, f1.v3, b0, b1, b2, b3);
    }
}

extern "C" void kernel_launch(void* const* d_in, const int* in_sizes, int n_in,
                              void* d_out, int out_size)
{
    // inputs (metadata order): t (1,), coords (bs, 8)
    const float* coords = (const float*)d_in[1];
    int bs = in_sizes[1] / 8;
    int pairs = (bs + 1) / 2;

    int threads = 256;
    int blocks  = (pairs + threads - 1) / threads;
    pendulum2_kernel<<<blocks, threads>>>(coords, (float*)d_out, bs);
}